// round 1
// baseline (speedup 1.0000x reference)
#include <cuda_runtime.h>

typedef unsigned long long ull;

#define BATCH 1024
#define TLEN  200
#define DDIM  128
#define HDIM  128
#define NXC   384                     // 256 gate cols + 128 cand cols
#define MROWS (BATCH * TLEN)          // 204800

// Scratch: x-projection [B*T, 384] (gate pre-act cols 0..255, cand pre-act cols 256..383)
__device__ float g_xproj[(size_t)MROWS * NXC];

// ---------- packed f32x2 helpers (Blackwell FFMA2 path) ----------
__device__ __forceinline__ ull dup2(float v) {
    ull r; asm("mov.b64 %0,{%1,%1};" : "=l"(r) : "f"(v)); return r;
}
__device__ __forceinline__ ull pack2(float x, float y) {
    ull r; asm("mov.b64 %0,{%1,%2};" : "=l"(r) : "f"(x), "f"(y)); return r;
}
__device__ __forceinline__ float2 unpack2(ull v) {
    float2 f; asm("mov.b64 {%0,%1},%2;" : "=f"(f.x), "=f"(f.y) : "l"(v)); return f;
}
__device__ __forceinline__ void ffma2(ull &d, ull a, ull b) {
    asm("fma.rn.f32x2 %0,%1,%2,%0;" : "+l"(d) : "l"(a), "l"(b));
}

__device__ __forceinline__ float fsigmoid(float z) {
    return __fdividef(1.0f, 1.0f + __expf(-z));
}
__device__ __forceinline__ float ftanh(float z) {
    // tanh(z) = 1 - 2/(e^{2z}+1); saturates correctly at +/-inf of __expf
    return 1.0f - __fdividef(2.0f, __expf(2.0f * z) + 1.0f);
}

// =====================================================================
// Phase 1: xproj[r, :] = x[r, :] @ Wx[128, 384] + bias   (r = b*T + t)
// Tiles: BM=128 rows x BN=128 cols, K=128 entirely in smem. grid=(3,1600)
// Tiles whose rows are all beyond seq_len are skipped (never read later).
// =====================================================================
__global__ void __launch_bounds__(256) dien_xproj_kernel(
    const float* __restrict__ X, const int* __restrict__ seqlen,
    const float* __restrict__ Wg, const float* __restrict__ bg,
    const float* __restrict__ Wc, const float* __restrict__ bc)
{
    extern __shared__ float sm[];
    float* xsT = sm;                 // [128 k][132 rows] (transposed, padded)
    float* ws  = sm + 128 * 132;     // [128 k][128 cols]

    const int tid = threadIdx.x;
    const int r0  = blockIdx.y * 128;
    const int ct  = blockIdx.x;      // 0,1 -> gate col tiles, 2 -> cand cols

    // --- seq_len skip: tile dead iff every row has t >= seq_len[b] ---
    __shared__ int anyv;
    if (tid == 0) anyv = 0;
    __syncthreads();
    if (tid < 128) {
        int r = r0 + tid;
        int b = r / TLEN, t = r - b * TLEN;
        if (t < seqlen[b]) anyv = 1;   // benign race: all write 1
    }
    __syncthreads();
    if (!anyv) return;

    // --- load x tile transposed: xsT[k][r] ---
    const float4* X4 = (const float4*)(X + (size_t)r0 * DDIM);
    #pragma unroll
    for (int idx = tid; idx < 4096; idx += 256) {
        int k4 = idx >> 7;           // 0..31
        int r  = idx & 127;          // warp: consecutive r -> conflict-free STS
        float4 v = X4[(size_t)r * 32 + k4];
        int kb = k4 * 4;
        xsT[(kb + 0) * 132 + r] = v.x;
        xsT[(kb + 1) * 132 + r] = v.y;
        xsT[(kb + 2) * 132 + r] = v.z;
        xsT[(kb + 3) * 132 + r] = v.w;
    }
    // --- load W tile: ws[k][c] ---
    if (ct < 2) {
        const float4* W4 = (const float4*)Wg;     // row = 64 float4
        #pragma unroll
        for (int idx = tid; idx < 4096; idx += 256) {
            int k = idx >> 5, c4 = idx & 31;
            *(float4*)&ws[k * 128 + c4 * 4] = W4[k * 64 + ct * 32 + c4];
        }
    } else {
        const float4* W4 = (const float4*)Wc;     // row = 32 float4
        #pragma unroll
        for (int idx = tid; idx < 4096; idx += 256) {
            int k = idx >> 5, c4 = idx & 31;
            *(float4*)&ws[k * 128 + c4 * 4] = W4[k * 32 + c4];
        }
    }
    __syncthreads();

    const int tx = tid & 15;   // col group: cols tx*8 .. tx*8+7
    const int ty = tid >> 4;   // row group: rows ty*8 .. ty*8+7

    // acc[row i][col pair p], init with bias (same bias for all rows)
    ull acc[8][4];
    {
        const float* bias = (ct < 2) ? (bg + ct * 128 + tx * 8) : (bc + tx * 8);
        #pragma unroll
        for (int p = 0; p < 4; p++) {
            ull bp = pack2(bias[2 * p], bias[2 * p + 1]);
            #pragma unroll
            for (int i = 0; i < 8; i++) acc[i][p] = bp;
        }
    }

    const float4*      a4 = (const float4*)xsT;        // idx k*33 + ty*2 (+0,+1)
    const ulonglong2*  b2 = (const ulonglong2*)ws;      // idx k*32 + tx*2 (+0,+1)

    #pragma unroll 2
    for (int k = 0; k < 128; k++) {
        float4 av0 = a4[k * 33 + ty * 2];
        float4 av1 = a4[k * 33 + ty * 2 + 1];
        ulonglong2 b01 = b2[k * 32 + tx * 2];
        ulonglong2 b23 = b2[k * 32 + tx * 2 + 1];
        ull A[8];
        A[0] = dup2(av0.x); A[1] = dup2(av0.y); A[2] = dup2(av0.z); A[3] = dup2(av0.w);
        A[4] = dup2(av1.x); A[5] = dup2(av1.y); A[6] = dup2(av1.z); A[7] = dup2(av1.w);
        #pragma unroll
        for (int i = 0; i < 8; i++) {
            ffma2(acc[i][0], A[i], b01.x);
            ffma2(acc[i][1], A[i], b01.y);
            ffma2(acc[i][2], A[i], b23.x);
            ffma2(acc[i][3], A[i], b23.y);
        }
    }

    // --- store ---
    #pragma unroll
    for (int i = 0; i < 8; i++) {
        size_t r = (size_t)(r0 + ty * 8 + i);
        float2 p0 = unpack2(acc[i][0]);
        float2 p1 = unpack2(acc[i][1]);
        float2 p2 = unpack2(acc[i][2]);
        float2 p3 = unpack2(acc[i][3]);
        float* dst = &g_xproj[r * NXC + ct * 128 + tx * 8];
        ((float4*)dst)[0] = make_float4(p0.x, p0.y, p1.x, p1.y);
        ((float4*)dst)[1] = make_float4(p2.x, p2.y, p3.x, p3.y);
    }
}

// =====================================================================
// Phase 2: recurrent scan. 128 CTAs, each owns 8 batch rows, all T steps.
// Recurrent weights (192 KB) + h / r*h / u state in SMEM. f32x2 lanes = row pairs.
// =====================================================================
__global__ void __launch_bounds__(256) dien_gru_kernel(
    const float* __restrict__ Wg, const float* __restrict__ Wc,
    const int* __restrict__ seqlen, float* __restrict__ out)
{
    extern __shared__ float sm[];
    float*  whg = sm;                              // [128][256]  h-part of W_gate
    float*  whc = sm + 32768;                      // [128][128]  h-part of W_cand
    float2* hp  = (float2*)(sm + 32768 + 16384);   // [4 pairs][128]  h (rows 2r,2r+1)
    float2* rhp = hp + 512;                        // [4][128]  r*h
    float2* up  = rhp + 512;                       // [4][128]  u

    const int tid   = threadIdx.x;
    const int rows0 = blockIdx.x * 8;

    // load recurrent weights (rows 128..255 of W_gate / W_cand)
    {
        const float4* src = (const float4*)(Wg + 128 * 256);
        for (int idx = tid; idx < 8192; idx += 256) ((float4*)whg)[idx] = src[idx];
        const float4* src2 = (const float4*)(Wc + 128 * 128);
        for (int idx = tid; idx < 4096; idx += 256) ((float4*)whc)[idx] = src2[idx];
    }
    for (int idx = tid; idx < 512; idx += 256) hp[idx] = make_float2(0.0f, 0.0f);

    int seq[8], maxseq = 0;
    #pragma unroll
    for (int i = 0; i < 8; i++) { seq[i] = seqlen[rows0 + i]; maxseq = max(maxseq, seq[i]); }
    __syncthreads();

    const int j  = tid;          // gate column 0..255 (r: j<128, u: j>=128)
    const int jc = tid & 127;    // cand column
    const int rh = tid >> 7;     // cand row-half: pairs 2rh, 2rh+1 (rows 4rh..4rh+3)

    const ulonglong2* hp2  = (const ulonglong2*)hp;   // [pair r]: idx r*64 + k2
    const ulonglong2* rhp2 = (const ulonglong2*)rhp;

    for (int t = 0; t < maxseq; t++) {
        // prefetch x-projections (consumed after the k-loops -> latency hidden)
        float xg[8], xc[4];
        #pragma unroll
        for (int i = 0; i < 8; i++)
            xg[i] = g_xproj[((size_t)(rows0 + i) * TLEN + t) * NXC + j];
        #pragma unroll
        for (int i = 0; i < 4; i++)
            xc[i] = g_xproj[((size_t)(rows0 + 4 * rh + i) * TLEN + t) * NXC + 256 + jc];

        // ---- gate GEMV: z[row][j] = sum_k h[row][k] * whg[k][j] ----
        ull acc[4] = {0ull, 0ull, 0ull, 0ull};
        #pragma unroll 4
        for (int k2 = 0; k2 < 64; k2++) {
            ulonglong2 a0 = hp2[k2];            // broadcast loads (same addr all threads)
            ulonglong2 a1 = hp2[64 + k2];
            ulonglong2 a2 = hp2[128 + k2];
            ulonglong2 a3 = hp2[192 + k2];
            ull b0 = dup2(whg[(2 * k2) * 256 + j]);
            ull b1 = dup2(whg[(2 * k2 + 1) * 256 + j]);
            ffma2(acc[0], a0.x, b0); ffma2(acc[0], a0.y, b1);
            ffma2(acc[1], a1.x, b0); ffma2(acc[1], a1.y, b1);
            ffma2(acc[2], a2.x, b0); ffma2(acc[2], a2.y, b1);
            ffma2(acc[3], a3.x, b0); ffma2(acc[3], a3.y, b1);
        }
        float s[8];
        #pragma unroll
        for (int r = 0; r < 4; r++) {
            float2 z = unpack2(acc[r]);
            s[2 * r]     = fsigmoid(z.x + xg[2 * r]);
            s[2 * r + 1] = fsigmoid(z.y + xg[2 * r + 1]);
        }
        if (j < 128) {                    // r-gate threads: stage r*h
            #pragma unroll
            for (int r = 0; r < 4; r++) {
                float2 hv = hp[r * 128 + j];
                rhp[r * 128 + j] = make_float2(s[2 * r] * hv.x, s[2 * r + 1] * hv.y);
            }
        } else {                          // u-gate threads: stage u
            #pragma unroll
            for (int r = 0; r < 4; r++)
                up[r * 128 + (j - 128)] = make_float2(s[2 * r], s[2 * r + 1]);
        }
        __syncthreads();

        // ---- cand GEMV: c[row][jc] = sum_k (r*h)[row][k] * whc[k][jc] ----
        ull acc2[2] = {0ull, 0ull};
        #pragma unroll 4
        for (int k2 = 0; k2 < 64; k2++) {
            ulonglong2 a0 = rhp2[(2 * rh) * 64 + k2];
            ulonglong2 a1 = rhp2[(2 * rh + 1) * 64 + k2];
            ull b0 = dup2(whc[(2 * k2) * 128 + jc]);
            ull b1 = dup2(whc[(2 * k2 + 1) * 128 + jc]);
            ffma2(acc2[0], a0.x, b0); ffma2(acc2[0], a0.y, b1);
            ffma2(acc2[1], a1.x, b0); ffma2(acc2[1], a1.y, b1);
        }
        #pragma unroll
        for (int p = 0; p < 2; p++) {
            int P = 2 * rh + p;                       // pair index: rows 2P, 2P+1
            float2 z = unpack2(acc2[p]);
            float cx = ftanh(z.x + xc[2 * p]);
            float cy = ftanh(z.y + xc[2 * p + 1]);
            float2 u2 = up[P * 128 + jc];
            float2 ho = hp[P * 128 + jc];
            float hnx = cx + u2.x * (ho.x - cx);      // u*h + (1-u)*c
            float hny = cy + u2.y * (ho.y - cy);
            bool v0 = t < seq[2 * P];
            bool v1 = t < seq[2 * P + 1];
            hp[P * 128 + jc] = make_float2(v0 ? hnx : ho.x, v1 ? hny : ho.y);
            if (v0) out[((size_t)(rows0 + 2 * P)     * TLEN + t) * HDIM + jc] = hnx;
            if (v1) out[((size_t)(rows0 + 2 * P + 1) * TLEN + t) * HDIM + jc] = hny;
        }
        __syncthreads();
    }
}

// =====================================================================
extern "C" void kernel_launch(void* const* d_in, const int* in_sizes, int n_in,
                              void* d_out, int out_size)
{
    const float* X   = (const float*)d_in[0];
    const int*   seq = (const int*)  d_in[1];
    const float* Wg  = (const float*)d_in[2];
    const float* bg  = (const float*)d_in[3];
    const float* Wc  = (const float*)d_in[4];
    const float* bc  = (const float*)d_in[5];
    float* out = (float*)d_out;
    (void)in_sizes; (void)n_in;

    const int SMEM1 = (128 * 132 + 128 * 128) * 4;                 // 133120 B
    const int SMEM2 = (32768 + 16384) * 4 + 3 * 512 * 8;           // 208896 B
    cudaFuncSetAttribute(dien_xproj_kernel, cudaFuncAttributeMaxDynamicSharedMemorySize, SMEM1);
    cudaFuncSetAttribute(dien_gru_kernel,   cudaFuncAttributeMaxDynamicSharedMemorySize, SMEM2);

    // outputs are zero for t >= seq_len; zero everything, phase 2 fills valid steps
    cudaMemsetAsync(d_out, 0, (size_t)out_size * sizeof(float));

    dim3 g1(3, MROWS / 128);   // 3 col-tiles x 1600 row-tiles
    dien_xproj_kernel<<<g1, 256, SMEM1>>>(X, seq, Wg, bg, Wc, bc);
    dien_gru_kernel<<<BATCH / 8, 256, SMEM2>>>(Wg, Wc, seq, out);
}

// round 2
// speedup vs baseline: 1.5064x; 1.5064x over previous
#include <cuda_runtime.h>

typedef unsigned long long ull;

#define BATCH 1024
#define TLEN  200
#define DDIM  128
#define HDIM  128
#define NXC   384                     // 256 gate cols + 128 cand cols
#define MROWS (BATCH * TLEN)          // 204800

// Scratch: x-projection [B*T, 384] (gate pre-act cols 0..255, cand pre-act cols 256..383)
__device__ float g_xproj[(size_t)MROWS * NXC];

// ---------- packed f32x2 helpers (Blackwell FFMA2 path) ----------
__device__ __forceinline__ ull dup2(float v) {
    ull r; asm("mov.b64 %0,{%1,%1};" : "=l"(r) : "f"(v)); return r;
}
__device__ __forceinline__ ull pack2(float x, float y) {
    ull r; asm("mov.b64 %0,{%1,%2};" : "=l"(r) : "f"(x), "f"(y)); return r;
}
__device__ __forceinline__ float2 unpack2(ull v) {
    float2 f; asm("mov.b64 {%0,%1},%2;" : "=f"(f.x), "=f"(f.y) : "l"(v)); return f;
}
__device__ __forceinline__ void ffma2(ull &d, ull a, ull b) {
    asm("fma.rn.f32x2 %0,%1,%2,%0;" : "+l"(d) : "l"(a), "l"(b));
}
__device__ __forceinline__ ull addf2(ull a, ull b) {
    ull r; asm("add.rn.f32x2 %0,%1,%2;" : "=l"(r) : "l"(a), "l"(b)); return r;
}
__device__ __forceinline__ float tanhap(float x) {
    float r; asm("tanh.approx.f32 %0,%1;" : "=f"(r) : "f"(x)); return r;
}
__device__ __forceinline__ float sigap(float x) {   // sigmoid(x) = 0.5 + 0.5*tanh(x/2)
    return fmaf(tanhap(0.5f * x), 0.5f, 0.5f);
}

// =====================================================================
// Phase 1: xproj[r, :] = x[r, :] @ Wx[128, 384] + bias   (r = b*T + t)
// Tiles: BM=128 rows x BN=128 cols. K chunked in 2x64 -> 66.5KB smem
// -> 2 CTAs/SM (16 warps). grid=(3,1600). Dead tiles skipped via seq_len.
// =====================================================================
__global__ void __launch_bounds__(256, 2) dien_xproj_kernel(
    const float* __restrict__ X, const int* __restrict__ seqlen,
    const float* __restrict__ Wg, const float* __restrict__ bg,
    const float* __restrict__ Wc, const float* __restrict__ bc)
{
    extern __shared__ float sm[];
    float* xsT = sm;                 // [64 k][132 rows] transposed, padded
    float* ws  = sm + 64 * 132;      // [64 k][128 cols]

    const int tid = threadIdx.x;
    const int r0  = blockIdx.y * 128;
    const int ct  = blockIdx.x;      // 0,1 -> gate col tiles, 2 -> cand cols

    // --- seq_len skip: tile dead iff every row has t >= seq_len[b] ---
    __shared__ int anyv;
    if (tid == 0) anyv = 0;
    __syncthreads();
    if (tid < 128) {
        int r = r0 + tid;
        int b = r / TLEN, t = r - b * TLEN;
        if (t < seqlen[b]) anyv = 1;
    }
    __syncthreads();
    if (!anyv) return;

    const int tx = tid & 15;   // col group: cols tx*8 .. tx*8+7
    const int ty = tid >> 4;   // row group: rows ty*8 .. ty*8+7

    // acc[row i][col pair p], init with bias
    ull acc[8][4];
    {
        const float* bias = (ct < 2) ? (bg + ct * 128 + tx * 8) : (bc + tx * 8);
        #pragma unroll
        for (int p = 0; p < 4; p++) {
            ull bp = pack2(bias[2 * p], bias[2 * p + 1]);
            #pragma unroll
            for (int i = 0; i < 8; i++) acc[i][p] = bp;
        }
    }

    const float4* X4 = (const float4*)(X + (size_t)r0 * DDIM);

    for (int c = 0; c < 2; c++) {
        // --- load x chunk transposed: xsT[k][r], k in [c*64, c*64+64) ---
        #pragma unroll
        for (int idx = tid; idx < 2048; idx += 256) {
            int k4 = idx >> 7;           // 0..15
            int r  = idx & 127;
            float4 v = X4[(size_t)r * 32 + c * 16 + k4];
            int kb = k4 * 4;
            xsT[(kb + 0) * 132 + r] = v.x;
            xsT[(kb + 1) * 132 + r] = v.y;
            xsT[(kb + 2) * 132 + r] = v.z;
            xsT[(kb + 3) * 132 + r] = v.w;
        }
        // --- load W chunk: ws[k][col] ---
        if (ct < 2) {
            const float4* W4 = (const float4*)Wg;     // row = 64 float4
            #pragma unroll
            for (int idx = tid; idx < 2048; idx += 256) {
                int k = idx >> 5, c4 = idx & 31;
                *(float4*)&ws[k * 128 + c4 * 4] = W4[(c * 64 + k) * 64 + ct * 32 + c4];
            }
        } else {
            const float4* W4 = (const float4*)Wc;     // row = 32 float4
            #pragma unroll
            for (int idx = tid; idx < 2048; idx += 256) {
                int k = idx >> 5, c4 = idx & 31;
                *(float4*)&ws[k * 128 + c4 * 4] = W4[(c * 64 + k) * 32 + c4];
            }
        }
        __syncthreads();

        const float4*     a4 = (const float4*)xsT;     // idx k*33 + ty*2 (+0,+1)
        const ulonglong2* b2 = (const ulonglong2*)ws;  // idx k*32 + tx*2 (+0,+1)

        #pragma unroll 4
        for (int k = 0; k < 64; k++) {
            float4 av0 = a4[k * 33 + ty * 2];
            float4 av1 = a4[k * 33 + ty * 2 + 1];
            ulonglong2 b01 = b2[k * 32 + tx * 2];
            ulonglong2 b23 = b2[k * 32 + tx * 2 + 1];
            ull A[8];
            A[0] = dup2(av0.x); A[1] = dup2(av0.y); A[2] = dup2(av0.z); A[3] = dup2(av0.w);
            A[4] = dup2(av1.x); A[5] = dup2(av1.y); A[6] = dup2(av1.z); A[7] = dup2(av1.w);
            #pragma unroll
            for (int i = 0; i < 8; i++) {
                ffma2(acc[i][0], A[i], b01.x);
                ffma2(acc[i][1], A[i], b01.y);
                ffma2(acc[i][2], A[i], b23.x);
                ffma2(acc[i][3], A[i], b23.y);
            }
        }
        __syncthreads();
    }

    // --- store ---
    #pragma unroll
    for (int i = 0; i < 8; i++) {
        size_t r = (size_t)(r0 + ty * 8 + i);
        float2 p0 = unpack2(acc[i][0]);
        float2 p1 = unpack2(acc[i][1]);
        float2 p2 = unpack2(acc[i][2]);
        float2 p3 = unpack2(acc[i][3]);
        float* dst = &g_xproj[r * NXC + ct * 128 + tx * 8];
        ((float4*)dst)[0] = make_float4(p0.x, p0.y, p1.x, p1.y);
        ((float4*)dst)[1] = make_float4(p2.x, p2.y, p3.x, p3.y);
    }
}

// =====================================================================
// Phase 2: recurrent scan. 128 CTAs x 512 threads, 8 batch rows each.
// Gate weights (64 floats/thread) REGISTER-RESIDENT for all timesteps.
// f32x2 lanes = adjacent batch-row pairs. k-split + smem tree reduction.
// =====================================================================
__global__ void __launch_bounds__(512, 1) dien_gru_kernel(
    const float* __restrict__ Wg, const float* __restrict__ Wc,
    const int* __restrict__ seqlen, float* __restrict__ out)
{
    extern __shared__ char smraw[];
    float* whc = (float*)smraw;                 // [128 k][128 col] cand h-weights, 64KB
    ull*   hp  = (ull*)(smraw + 65536);         // [4 pair][128 k] h           4KB
    ull*   rhp = hp + 512;                      // [4 pair][128 k] r*h         4KB
    ull*   red = rhp + 512;                     // reduction stage, 4096 ull, 32KB

    const int tid   = threadIdx.x;
    const int rows0 = blockIdx.x * 8;

    // ---- load cand weights into smem, zero h ----
    for (int i = tid; i < 128 * 128; i += 512) whc[i] = Wc[128 * 128 + i];
    hp[tid] = 0ull;

    // ---- gate mapping: 2 cols (jc, jc+128), k in [q*32, q*32+32) ----
    const int jc = tid & 127;
    const int q  = tid >> 7;            // 0..3 (also the epilogue pair index)
    const int k0 = q * 32;

    float wgr[32], wgu[32];             // register-resident gate weights
    #pragma unroll
    for (int i = 0; i < 32; i++) {
        wgr[i] = Wg[(size_t)(128 + k0 + i) * 256 + jc];
        wgu[i] = Wg[(size_t)(128 + k0 + i) * 256 + jc + 128];
    }

    // ---- cand mapping: 2 cols (jc2, jc2+64), k in [q2*16, q2*16+16) ----
    const int jc2 = tid & 63;
    const int q2  = tid >> 6;           // 0..7
    const int kc0 = q2 * 16;

    // ---- epilogue mapping: pair p = q, column jc ----
    const int sq0 = seqlen[rows0 + 2 * q];
    const int sq1 = seqlen[rows0 + 2 * q + 1];
    int maxseq = 0;
    #pragma unroll
    for (int i = 0; i < 8; i++) maxseq = max(maxseq, seqlen[rows0 + i]);
    __syncthreads();

    const float* xb0 = g_xproj + ((size_t)(rows0 + 2 * q)     * TLEN) * NXC;
    const float* xb1 = g_xproj + ((size_t)(rows0 + 2 * q + 1) * TLEN) * NXC;

    const ulonglong2* hpv = (const ulonglong2*)hp  + (k0  >> 1);
    const ulonglong2* rhv = (const ulonglong2*)rhp + (kc0 >> 1);

    for (int t = 0; t < maxseq; t++) {
        // prefetch x-projections (consumed ~2000 cycles later in epilogues)
        const float* x0 = xb0 + (size_t)t * NXC;
        const float* x1 = xb1 + (size_t)t * NXC;
        float xr0 = x0[jc],       xr1 = x1[jc];
        float xu0 = x0[jc + 128], xu1 = x1[jc + 128];
        float xc0 = x0[jc + 256], xc1 = x1[jc + 256];

        // ---- gate GEMV partials: 2 cols x 4 row-pairs, 32 k's from regs ----
        ull accr[4] = {0,0,0,0}, accu[4] = {0,0,0,0};
        #pragma unroll
        for (int i = 0; i < 16; i++) {
            ulonglong2 a0 = hpv[i];
            ulonglong2 a1 = hpv[64 + i];
            ulonglong2 a2 = hpv[128 + i];
            ulonglong2 a3 = hpv[192 + i];
            ull w0 = dup2(wgr[2*i]), w1 = dup2(wgr[2*i+1]);
            ull v0 = dup2(wgu[2*i]), v1 = dup2(wgu[2*i+1]);
            ffma2(accr[0], a0.x, w0); ffma2(accr[0], a0.y, w1);
            ffma2(accr[1], a1.x, w0); ffma2(accr[1], a1.y, w1);
            ffma2(accr[2], a2.x, w0); ffma2(accr[2], a2.y, w1);
            ffma2(accr[3], a3.x, w0); ffma2(accr[3], a3.y, w1);
            ffma2(accu[0], a0.x, v0); ffma2(accu[0], a0.y, v1);
            ffma2(accu[1], a1.x, v0); ffma2(accu[1], a1.y, v1);
            ffma2(accu[2], a2.x, v0); ffma2(accu[2], a2.y, v1);
            ffma2(accu[3], a3.x, v0); ffma2(accu[3], a3.y, v1);
        }
        // stage partials: red[((q*2+col)*4+pair)*128 + jc]
        {
            ull* st = red + (q * 8) * 128 + jc;
            #pragma unroll
            for (int P = 0; P < 4; P++) { st[P * 128] = accr[P]; st[(4 + P) * 128] = accu[P]; }
        }
        __syncthreads();

        // ---- gate epilogue: thread (jc, p=q) finishes rows 2p,2p+1 at col jc ----
        ull zr, zu;
        {
            const ull* rd = red + q * 128 + jc;     // pair stride 128, q' stride 1024
            zr = rd[0];           zu = rd[512];
            zr = addf2(zr, rd[1024]);  zu = addf2(zu, rd[1536]);
            zr = addf2(zr, rd[2048]);  zu = addf2(zu, rd[2560]);
            zr = addf2(zr, rd[3072]);  zu = addf2(zu, rd[3584]);
        }
        float2 Zr = unpack2(zr), Zu = unpack2(zu);
        float r0 = sigap(Zr.x + xr0), r1 = sigap(Zr.y + xr1);
        float u0 = sigap(Zu.x + xu0), u1 = sigap(Zu.y + xu1);
        ull hov = hp[q * 128 + jc];
        float2 Ho = unpack2(hov);
        rhp[q * 128 + jc] = pack2(r0 * Ho.x, r1 * Ho.y);
        __syncthreads();

        // ---- cand GEMV partials: cols jc2, jc2+64; 16 k's; weights from smem ----
        ull accA[4] = {0,0,0,0}, accB[4] = {0,0,0,0};
        #pragma unroll
        for (int i = 0; i < 8; i++) {
            ulonglong2 a0 = rhv[i];
            ulonglong2 a1 = rhv[64 + i];
            ulonglong2 a2 = rhv[128 + i];
            ulonglong2 a3 = rhv[192 + i];
            const float* wrow0 = whc + (kc0 + 2*i) * 128;
            const float* wrow1 = wrow0 + 128;
            ull wA0 = dup2(wrow0[jc2]),      wA1 = dup2(wrow1[jc2]);
            ull wB0 = dup2(wrow0[jc2 + 64]), wB1 = dup2(wrow1[jc2 + 64]);
            ffma2(accA[0], a0.x, wA0); ffma2(accA[0], a0.y, wA1);
            ffma2(accA[1], a1.x, wA0); ffma2(accA[1], a1.y, wA1);
            ffma2(accA[2], a2.x, wA0); ffma2(accA[2], a2.y, wA1);
            ffma2(accA[3], a3.x, wA0); ffma2(accA[3], a3.y, wA1);
            ffma2(accB[0], a0.x, wB0); ffma2(accB[0], a0.y, wB1);
            ffma2(accB[1], a1.x, wB0); ffma2(accB[1], a1.y, wB1);
            ffma2(accB[2], a2.x, wB0); ffma2(accB[2], a2.y, wB1);
            ffma2(accB[3], a3.x, wB0); ffma2(accB[3], a3.y, wB1);
        }
        // stage: red[((q2*2+col)*4+pair)*64 + jc2]
        {
            ull* st = red + (q2 * 8) * 64 + jc2;
            #pragma unroll
            for (int P = 0; P < 4; P++) { st[P * 64] = accA[P]; st[(4 + P) * 64] = accB[P]; }
        }
        __syncthreads();

        // ---- cand epilogue + state update: thread (jc, p=q) ----
        {
            int c2  = jc >> 6;            // which col half
            int j2e = jc & 63;
            const ull* rd = red + (c2 * 4 + q) * 64 + j2e;   // q2 stride 512
            ull zc = rd[0];
            #pragma unroll
            for (int qq = 1; qq < 8; qq++) zc = addf2(zc, rd[qq * 512]);
            float2 Zc = unpack2(zc);
            float c0 = tanhap(Zc.x + xc0);
            float c1 = tanhap(Zc.y + xc1);
            float hn0 = fmaf(u0, Ho.x - c0, c0);   // u*h + (1-u)*c
            float hn1 = fmaf(u1, Ho.y - c1, c1);
            bool v0 = t < sq0, v1 = t < sq1;
            hp[q * 128 + jc] = pack2(v0 ? hn0 : Ho.x, v1 ? hn1 : Ho.y);
            if (v0) out[((size_t)(rows0 + 2 * q)     * TLEN + t) * HDIM + jc] = hn0;
            if (v1) out[((size_t)(rows0 + 2 * q + 1) * TLEN + t) * HDIM + jc] = hn1;
        }
        __syncthreads();
    }
}

// =====================================================================
extern "C" void kernel_launch(void* const* d_in, const int* in_sizes, int n_in,
                              void* d_out, int out_size)
{
    const float* X   = (const float*)d_in[0];
    const int*   seq = (const int*)  d_in[1];
    const float* Wg  = (const float*)d_in[2];
    const float* bg  = (const float*)d_in[3];
    const float* Wc  = (const float*)d_in[4];
    const float* bc  = (const float*)d_in[5];
    float* out = (float*)d_out;
    (void)in_sizes; (void)n_in;

    const int SMEM1 = (64 * 132 + 64 * 128) * 4;                  // 66560 B
    const int SMEM2 = 65536 + 4096 + 4096 + 32768;                // 106496 B
    cudaFuncSetAttribute(dien_xproj_kernel, cudaFuncAttributeMaxDynamicSharedMemorySize, SMEM1);
    cudaFuncSetAttribute(dien_gru_kernel,   cudaFuncAttributeMaxDynamicSharedMemorySize, SMEM2);

    // outputs are zero for t >= seq_len; zero everything, phase 2 fills valid steps
    cudaMemsetAsync(d_out, 0, (size_t)out_size * sizeof(float));

    dim3 g1(3, MROWS / 128);   // 3 col-tiles x 1600 row-tiles
    dien_xproj_kernel<<<g1, 256, SMEM1>>>(X, seq, Wg, bg, Wc, bc);
    dien_gru_kernel<<<BATCH / 8, 512, SMEM2>>>(Wg, Wc, seq, out);
}